// round 15
// baseline (speedup 1.0000x reference)
#include <cuda_runtime.h>
#include <math_constants.h>

#define BB 32
#define NN 1024
#define FF 128
#define DG 64
#define TK 15
#define MTOT 256   // 64 q-dims + 64 k-dims + 128 h-dims
#define NEDGE (BB * NN * TK)

typedef unsigned long long u64;

// packed f32x2 helpers (Blackwell FFMA2 — only reachable via explicit PTX)
__device__ __forceinline__ u64 pk2(float lo, float hi) {
    u64 r; asm("mov.b64 %0, {%1, %2};" : "=l"(r) : "f"(lo), "f"(hi)); return r;
}
__device__ __forceinline__ void upk2(u64 v, float& lo, float& hi) {
    asm("mov.b64 {%0, %1}, %2;" : "=f"(lo), "=f"(hi) : "l"(v));
}
__device__ __forceinline__ void fma2(u64& d, u64 a, u64 b) {
    asm("fma.rn.f32x2 %0, %1, %2, %0;" : "+l"(d) : "l"(a), "l"(b));
}
// 16B async copy global->shared (LDGSTS)
__device__ __forceinline__ void cp16(unsigned int saddr, const void* gptr) {
    asm volatile("cp.async.ca.shared.global [%0], [%1], 16;" :: "r"(saddr), "l"(gptr));
}

// ---- scratch (static device globals; no allocation allowed) ----
__device__ float g_WT [FF * MTOT];     // transposed combined weights [f][dcomb]
__device__ float g_q  [BB * NN * DG];  // [node][d]
__device__ float g_kkT[BB * DG * NN];  // transposed: [b][d][node]
__device__ float g_h  [BB * NN * FF];
__device__ float g_acc[BB * NN * FF];
__device__ int   g_topk[NEDGE];
__device__ float g_deg [BB * NN];
__device__ float g_dinv[BB * NN];
__device__ int   g_off [BB * NN];      // CSR offsets (global edge index)
__device__ int   g_cur [BB * NN];      // fill cursors
__device__ int   g_esrc[NEDGE];        // CSR edge source (global node id b*NN+src)
__device__ float g_sp [(long)BB * NN * NN];  // spilled score rows (128MB, streaming)

// ---------------------------------------------------------------------------
// Prep: build WT[f][d] = {Wq[d][f], Wk[d-64][f], Wg[d-128][f]}; init deg=2
// (module self-loop + GCNConv internal self-loop). FF*MTOT == BB*NN == 32768.
// ---------------------------------------------------------------------------
__global__ void k_prep(const float* __restrict__ Wq, const float* __restrict__ Wk,
                       const float* __restrict__ Wg) {
    int idx = blockIdx.x * blockDim.x + threadIdx.x;   // 0..32767
    int f = idx >> 8;
    int d = idx & 255;
    float v;
    if (d < 64)       v = Wq[d * FF + f];
    else if (d < 128) v = Wk[(d - 64) * FF + f];
    else              v = Wg[(d - 128) * FF + f];
    g_WT[f * MTOT + d] = v;
    g_deg[idx] = 2.0f;
}

// zero the CSR fill cursors. Idempotent; launched TWICE so the bench's ncu
// capture at launch index 3 lands on k_qkh this round.
__global__ void k_zero() {
    g_cur[blockIdx.x * 256 + threadIdx.x] = 0;
}

// ---------------------------------------------------------------------------
// Fused GEMM: C[d][n] = sum_f WT[f][d] * x[b][f][n]  (per batch), FFMA2 core.
// q -> g_q [node][d] (+bq);  k -> g_kkT [d][node] (+bk);  h -> g_h [node][f].
// R14 profile: L1=86.5% (smem-BW-bound). Fix: the two Bs LDS.64s (2-way
// bank-conflicted, 4 wavefronts) are merged into ONE conflict-free LDS.128
// (2 wavefronts) — cols tx*4..tx*4+3 are contiguous. Values and accumulation
// order bitwise unchanged.
// ---------------------------------------------------------------------------
__global__ void __launch_bounds__(256, 3) k_qkh(const float* __restrict__ x,
                                                const float* __restrict__ bq,
                                                const float* __restrict__ bk) {
    extern __shared__ __align__(16) float sq[];
    float* As = sq;               // [128][64]  32KB  (k-major, m inner)
    float* Bs = sq + FF * 64;     // [128][64]  32KB
    const int m0 = blockIdx.x * 64;
    const int n0 = blockIdx.y * 64;
    const int b  = blockIdx.z;
    const int tid = threadIdx.x;
    const int tx = tid & 15;    // n quad
    const int ty = tid >> 4;    // m quad

    const unsigned int As_s = (unsigned int)__cvta_generic_to_shared(As);
    const unsigned int Bs_s = (unsigned int)__cvta_generic_to_shared(Bs);
    // async fill: 128 k-rows x 16 float4 each, for As and Bs
    for (int u = tid; u < FF * 16; u += 256) {
        int k = u >> 4, g = u & 15;
        unsigned int soff = (unsigned)(k * 64 + g * 4) * 4;
        cp16(As_s + soff, &g_WT[k * MTOT + m0 + g * 4]);
        cp16(Bs_s + soff, &x[((long)(b * FF + k)) * NN + n0 + g * 4]);
    }
    asm volatile("cp.async.commit_group;" ::: "memory");

    u64 acc2[4][2];             // [m][n-pair], each holds cols (0,1)/(2,3)
    #pragma unroll
    for (int i = 0; i < 4; i++) { acc2[i][0] = 0ull; acc2[i][1] = 0ull; }

    asm volatile("cp.async.wait_group 0;" ::: "memory");
    __syncthreads();

    #pragma unroll 8
    for (int k = 0; k < FF; k++) {
        float4 a  = *(const float4*)&As[k * 64 + ty * 4];
        ulonglong2 bb = *(const ulonglong2*)&Bs[k * 64 + tx * 4];  // one LDS.128
        u64 b0 = bb.x, b1 = bb.y;
        float av[4] = {a.x, a.y, a.z, a.w};
        #pragma unroll
        for (int i = 0; i < 4; i++) {
            u64 aa = pk2(av[i], av[i]);
            fma2(acc2[i][0], aa, b0);
            fma2(acc2[i][1], aa, b1);
        }
    }

    float acc[4][4];
    #pragma unroll
    for (int i = 0; i < 4; i++) {
        upk2(acc2[i][0], acc[i][0], acc[i][1]);
        upk2(acc2[i][1], acc[i][2], acc[i][3]);
    }

    const int d0 = m0 + ty * 4;   // combined dim base (multiple of 4)
    float4 bias = make_float4(0.f, 0.f, 0.f, 0.f);
    if (m0 == 0)       bias = *(const float4*)&bq[d0];
    else if (m0 == 64) bias = *(const float4*)&bk[d0 - 64];

    if (m0 == 64) {
        // k part: store transposed rows [d][n], float4 along n
        float bb4[4] = {bias.x, bias.y, bias.z, bias.w};
        #pragma unroll
        for (int i = 0; i < 4; i++) {
            int dd = d0 - 64 + i;
            float4 v = make_float4(acc[i][0] + bb4[i], acc[i][1] + bb4[i],
                                   acc[i][2] + bb4[i], acc[i][3] + bb4[i]);
            *(float4*)&g_kkT[((long)(b * DG + dd)) * NN + n0 + tx * 4] = v;
        }
    } else {
        #pragma unroll
        for (int jj = 0; jj < 4; jj++) {
            int n = n0 + tx * 4 + jj;
            float4 v = make_float4(acc[0][jj] + bias.x, acc[1][jj] + bias.y,
                                   acc[2][jj] + bias.z, acc[3][jj] + bias.w);
            long nodeBase = (long)(b * NN + n);
            if (m0 == 0) *(float4*)&g_q [nodeBase * DG + d0]         = v;
            else         *(float4*)&g_h [nodeBase * FF + (d0 - 128)] = v;
        }
    }
}

// ---------------------------------------------------------------------------
// Top-15 selection. Per-lane candidates seeded from an inline-maintained
// top-2; 15 warp-argmax extractions with (value desc, index asc) order
// matching jax.lax.top_k. When a lane must yield its 3rd+ value it rescans
// its own 32 scores from the global spill row (rare: E ~0.44/row).
// ---------------------------------------------------------------------------
__device__ __forceinline__ void select15(float b1v, int b1i, float b2v, int b2i,
                                         const float* __restrict__ row_sp,
                                         int lane, int b, int r) {
    const float NEG = -CUDART_INF_F;
    const int BIGI = 1 << 30;
    float lv = CUDART_INF_F; int li = -1;    // lane's last extracted (exclusion bound)
    float cv = b1v; int ci = b1i;            // candidate
    float sv = b2v; int si = b2i;            // spare
    for (int it = 0; it < TK; it++) {
        float mv = cv; int mi = ci;
        #pragma unroll
        for (int off = 16; off; off >>= 1) {
            float ov = __shfl_xor_sync(0xffffffffu, mv, off);
            int   oi = __shfl_xor_sync(0xffffffffu, mi, off);
            if (ov > mv || (ov == mv && oi < mi)) { mv = ov; mi = oi; }
        }
        if (lane == 0) {
            g_topk[(b * NN + r) * TK + it] = mi;
            atomicAdd(&g_deg[b * NN + mi], 1.0f);   // integer-valued: exact
        }
        if (ci == mi) {                      // unique owner
            lv = mv; li = mi;
            cv = sv; ci = si; sv = NEG; si = BIGI;
        }
        bool need = (ci == BIGI);
        if (__any_sync(0xffffffffu, need)) {
            if (need) {
                cv = NEG; ci = BIGI;
                #pragma unroll
                for (int t8 = 0; t8 < 8; t8++) {
                    float4 vv = __ldg((const float4*)&row_sp[t8 * 128 + lane * 4]);
                    float va[4] = {vv.x, vv.y, vv.z, vv.w};
                    #pragma unroll
                    for (int j = 0; j < 4; j++) {
                        int col = t8 * 128 + lane * 4 + j;
                        float v = va[j];
                        bool after  = (v < lv) || (v == lv && col > li);
                        bool better = (v > cv) || (v == cv && col < ci);
                        if (after && better) { cv = v; ci = col; }
                    }
                }
            }
        }
    }
}

// ---------------------------------------------------------------------------
// Fused scores + top-15 — UNCHANGED from R13 (best measured: 221 us).
// R10 datapath (4 rows/warp) + cp.async double-buffered k-tile prefetch +
// 3 blocks/SM. 1/sqrt(DG) scale omitted (top-k invariant). Diagonal -inf.
// ---------------------------------------------------------------------------
__global__ void __launch_bounds__(256, 3) k_topk() {
    extern __shared__ __align__(16) float sdyn[];
    float* qs  = sdyn;                    // [32][DG]  8KB
    float* ks0 = sdyn + 32 * DG;          // [DG][132] 33.8KB
    float* ks1 = ks0 + DG * 132;          // [DG][132] 33.8KB
    const int b  = blockIdx.y;
    const int r0 = blockIdx.x * 32;
    const int tid  = threadIdx.x;
    const int lane = tid & 31;
    const int w    = tid >> 5;
    const int rbase = r0 + 4 * w;

    for (int idx = tid; idx < 32 * DG; idx += 256)
        qs[idx] = g_q[(b * NN + r0 + (idx >> 6)) * DG + (idx & 63)];  // idx=row*64+d

    const unsigned int ks0_s = (unsigned int)__cvta_generic_to_shared(ks0);
    const unsigned int ks1_s = (unsigned int)__cvta_generic_to_shared(ks1);

    // prefetch tile 0 into ks0
    {
        for (int u = tid; u < DG * 32; u += 256) {
            int d = u >> 5, ms = u & 31;
            cp16(ks0_s + (unsigned)(d * 132 + ms * 4) * 4,
                 &g_kkT[((long)(b * DG + d)) * NN + ms * 4]);
        }
        asm volatile("cp.async.commit_group;" ::: "memory");
    }

    const float NEG = -CUDART_INF_F;
    const int BIGI = 1 << 30;
    float b1v[4], b2v[4]; int b1i[4], b2i[4];
    #pragma unroll
    for (int i = 0; i < 4; i++) { b1v[i] = NEG; b1i[i] = BIGI; b2v[i] = NEG; b2i[i] = BIGI; }

    const long spbase = ((long)(b * NN)) << 10;
    const float* qrow = &qs[4 * w * DG];

    #pragma unroll
    for (int t = 0; t < 8; t++) {
        const int m0 = t * 128;
        const float* kcur = (t & 1) ? ks1 : ks0;
        asm volatile("cp.async.wait_group 0;" ::: "memory");
        __syncthreads();                       // tile t resident block-wide
        if (t < 7) {                           // prefetch tile t+1 into other buf
            unsigned int dst_s = (t & 1) ? ks0_s : ks1_s;
            const int m1 = m0 + 128;
            for (int u = tid; u < DG * 32; u += 256) {
                int d = u >> 5, ms = u & 31;
                cp16(dst_s + (unsigned)(d * 132 + ms * 4) * 4,
                     &g_kkT[((long)(b * DG + d)) * NN + m1 + ms * 4]);
            }
            asm volatile("cp.async.commit_group;" ::: "memory");
        }

        u64 accA[4] = {0ull, 0ull, 0ull, 0ull};   // rows 0..3, cols (lane*4+0,+1)
        u64 accB[4] = {0ull, 0ull, 0ull, 0ull};   // rows 0..3, cols (lane*4+2,+3)

        #pragma unroll 4
        for (int d4 = 0; d4 < DG; d4 += 4) {
            float4 q0 = *(const float4*)&qrow[0 * DG + d4];   // broadcast LDS.128
            float4 q1 = *(const float4*)&qrow[1 * DG + d4];
            float4 q2 = *(const float4*)&qrow[2 * DG + d4];
            float4 q3 = *(const float4*)&qrow[3 * DG + d4];
            float qv0[4] = {q0.x, q0.y, q0.z, q0.w};
            float qv1[4] = {q1.x, q1.y, q1.z, q1.w};
            float qv2[4] = {q2.x, q2.y, q2.z, q2.w};
            float qv3[4] = {q3.x, q3.y, q3.z, q3.w};
            #pragma unroll
            for (int j = 0; j < 4; j++) {
                ulonglong2 kk = *(const ulonglong2*)&kcur[(d4 + j) * 132 + lane * 4];
                u64 kA = kk.x, kB = kk.y;                     // one LDS.128
                u64 qq0 = pk2(qv0[j], qv0[j]);
                u64 qq1 = pk2(qv1[j], qv1[j]);
                u64 qq2 = pk2(qv2[j], qv2[j]);
                u64 qq3 = pk2(qv3[j], qv3[j]);
                fma2(accA[0], qq0, kA);  fma2(accB[0], qq0, kB);
                fma2(accA[1], qq1, kA);  fma2(accB[1], qq1, kB);
                fma2(accA[2], qq2, kA);  fma2(accB[2], qq2, kB);
                fma2(accA[3], qq3, kA);  fma2(accB[3], qq3, kB);
            }
        }

        const int c0 = m0 + lane * 4;
        #pragma unroll
        for (int i = 0; i < 4; i++) {
            const int r = rbase + i;
            float v0, v1, v2, v3;
            upk2(accA[i], v0, v1); upk2(accB[i], v2, v3);
            if (c0 + 0 == r) v0 = NEG;
            if (c0 + 1 == r) v1 = NEG;
            if (c0 + 2 == r) v2 = NEG;
            if (c0 + 3 == r) v3 = NEG;
            // spill masked scores (streaming; read back only on rare rescans)
            *(float4*)&g_sp[spbase + (((long)r) << 10) + c0] =
                make_float4(v0, v1, v2, v3);
            // inline top-2 merge, ascending column order
            float va[4] = {v0, v1, v2, v3};
            #pragma unroll
            for (int j = 0; j < 4; j++) {
                float v = va[j]; int col = c0 + j;
                if (v > b1v[i])      { b2v[i] = b1v[i]; b2i[i] = b1i[i]; b1v[i] = v; b1i[i] = col; }
                else if (v > b2v[i]) { b2v[i] = v; b2i[i] = col; }
            }
        }
        __syncthreads();      // all warps done with kcur before it is refilled
    }

    #pragma unroll
    for (int i = 0; i < 4; i++) {
        const int r = rbase + i;
        select15(b1v[i], b1i[i], b2v[i], b2i[i],
                 &g_sp[spbase + (((long)r) << 10)], lane, b, r);
    }
}

// ---------------------------------------------------------------------------
// CSR offsets: per-batch exclusive scan of in-edge counts (deg-2); also dinv.
// One block per batch, 1024 threads (Hillis-Steele scan).
// ---------------------------------------------------------------------------
__global__ void __launch_bounds__(1024) k_offs() {
    __shared__ int s[1024];
    const int b = blockIdx.x, n = threadIdx.x, i = b * NN + n;
    float dg = g_deg[i];
    g_dinv[i] = rsqrtf(dg);
    int c = (int)dg - 2;
    s[n] = c;
    __syncthreads();
    for (int off = 1; off < 1024; off <<= 1) {
        int v = (n >= off) ? s[n - off] : 0;
        __syncthreads();
        s[n] += v;
        __syncthreads();
    }
    g_off[i] = b * NN * TK + s[n] - c;   // exclusive
}

// CSR fill: thread per edge, slot via int atomic cursor.
__global__ void k_fill() {
    int e = blockIdx.x * 256 + threadIdx.x;   // < NEDGE
    int bnsrc = e / TK;                       // b*NN + src
    int b = bnsrc >> 10;
    int tgt = g_topk[e];
    int bt = (b << 10) + tgt;
    int pos = atomicAdd(&g_cur[bt], 1);
    g_esrc[g_off[bt] + pos] = bnsrc;
}

// ---------------------------------------------------------------------------
// Gather: block per target node, 128 threads (one per feature). Coalesced
// 512B row reads of h[src], register accumulate, single store. No fp atomics.
// out_row = dinv[t] * ( sum_e h[src]*dinv[src] + 2*dinv[t]*h[t] )
// ---------------------------------------------------------------------------
__global__ void __launch_bounds__(128) k_gather() {
    const int t = blockIdx.x;        // global node id b*NN+n
    const int f = threadIdx.x;
    const float dt = g_dinv[t];
    const int cnt = (int)g_deg[t] - 2;
    const int off = g_off[t];
    float acc = 2.0f * dt * g_h[(long)t * FF + f];
    int j = 0;
    for (; j + 4 <= cnt; j += 4) {
        int s0 = g_esrc[off + j],     s1 = g_esrc[off + j + 1];
        int s2 = g_esrc[off + j + 2], s3 = g_esrc[off + j + 3];
        float e0 = g_dinv[s0], e1 = g_dinv[s1], e2 = g_dinv[s2], e3 = g_dinv[s3];
        float h0 = g_h[(long)s0 * FF + f], h1 = g_h[(long)s1 * FF + f];
        float h2 = g_h[(long)s2 * FF + f], h3 = g_h[(long)s3 * FF + f];
        acc += h0 * e0; acc += h1 * e1; acc += h2 * e2; acc += h3 * e3;
    }
    for (; j < cnt; j++) {
        int s = g_esrc[off + j];
        acc += g_h[(long)s * FF + f] * g_dinv[s];
    }
    g_acc[(long)t * FF + f] = acc * dt;
}

// out[b][f][n] = acc[b][n][f] + bg[f]   (tiled transpose)
__global__ void k_out(float* __restrict__ out, const float* __restrict__ bg) {
    __shared__ float tile[32][33];
    const int n0 = blockIdx.x * 32, f0 = blockIdx.y * 32, b = blockIdx.z;
    const int tx = threadIdx.x, ty = threadIdx.y;   // 32 x 8
    #pragma unroll
    for (int ii = 0; ii < 4; ii++) {
        int n = n0 + ty + ii * 8;
        tile[ty + ii * 8][tx] = g_acc[(long)(b * NN + n) * FF + f0 + tx];
    }
    __syncthreads();
    #pragma unroll
    for (int ii = 0; ii < 4; ii++) {
        int f = f0 + ty + ii * 8;
        out[(long)(b * FF + f) * NN + n0 + tx] = tile[tx][ty + ii * 8] + bg[f];
    }
}

// ---------------------------------------------------------------------------
extern "C" void kernel_launch(void* const* d_in, const int* in_sizes, int n_in,
                              void* d_out, int out_size) {
    const float* x  = (const float*)d_in[0];
    const float* Wq = (const float*)d_in[1];
    const float* bq = (const float*)d_in[2];
    const float* Wk = (const float*)d_in[3];
    const float* bk = (const float*)d_in[4];
    const float* Wg = (const float*)d_in[5];
    const float* bg = (const float*)d_in[6];
    float* out = (float*)d_out;

    const int TOPK_SMEM = (32 * DG + 2 * DG * 132) * 4;   // 75,776 B
    const int QKH_SMEM  = 2 * FF * 64 * 4;                // 65,536 B
    cudaFuncSetAttribute(k_topk, cudaFuncAttributeMaxDynamicSharedMemorySize,
                         TOPK_SMEM);
    cudaFuncSetAttribute(k_qkh, cudaFuncAttributeMaxDynamicSharedMemorySize,
                         QKH_SMEM);

    k_prep<<<(FF * MTOT) / 256, 256>>>(Wq, Wk, Wg);              // idx 0
    k_zero<<<(BB * NN) / 256, 256>>>();                          // idx 1
    k_zero<<<(BB * NN) / 256, 256>>>();                          // idx 2 (idempotent; aligns ncu idx 3)
    k_qkh<<<dim3(MTOT / 64, NN / 64, BB), 256, QKH_SMEM>>>(x, bq, bk); // idx 3 (ncu capture)
    k_topk<<<dim3(NN / 32, BB), 256, TOPK_SMEM>>>();             // idx 4
    k_offs<<<BB, 1024>>>();                                      // idx 5
    k_fill<<<NEDGE / 256, 256>>>();                              // idx 6
    k_gather<<<BB * NN, 128>>>();                                // idx 7
    k_out<<<dim3(NN / 32, FF / 32, BB), dim3(32, 8)>>>(out, bg); // idx 8
}

// round 16
// speedup vs baseline: 1.0488x; 1.0488x over previous
#include <cuda_runtime.h>
#include <math_constants.h>

#define BB 32
#define NN 1024
#define FF 128
#define DG 64
#define TK 15
#define MTOT 256   // 64 q-dims + 64 k-dims + 128 h-dims
#define NEDGE (BB * NN * TK)

typedef unsigned long long u64;

// packed f32x2 helpers (Blackwell FFMA2 — only reachable via explicit PTX)
__device__ __forceinline__ u64 pk2(float lo, float hi) {
    u64 r; asm("mov.b64 %0, {%1, %2};" : "=l"(r) : "f"(lo), "f"(hi)); return r;
}
__device__ __forceinline__ void upk2(u64 v, float& lo, float& hi) {
    asm("mov.b64 {%0, %1}, %2;" : "=f"(lo), "=f"(hi) : "l"(v));
}
__device__ __forceinline__ void fma2(u64& d, u64 a, u64 b) {
    asm("fma.rn.f32x2 %0, %1, %2, %0;" : "+l"(d) : "l"(a), "l"(b));
}
// 16B async copy global->shared (LDGSTS)
__device__ __forceinline__ void cp16(unsigned int saddr, const void* gptr) {
    asm volatile("cp.async.ca.shared.global [%0], [%1], 16;" :: "r"(saddr), "l"(gptr));
}

// ---- scratch (static device globals; no allocation allowed) ----
__device__ float g_WT [FF * MTOT];     // transposed combined weights [f][dcomb]
__device__ float g_q  [BB * NN * DG];  // [node][d]
__device__ float g_kkT[BB * DG * NN];  // transposed: [b][d][node]
__device__ float g_h  [BB * NN * FF];
__device__ float g_acc[BB * NN * FF];
__device__ int   g_topk[NEDGE];
__device__ float g_deg [BB * NN];
__device__ float g_dinv[BB * NN];
__device__ int   g_off [BB * NN];      // CSR offsets (global edge index)
__device__ int   g_cur [BB * NN];      // fill cursors
__device__ int   g_esrc[NEDGE];        // CSR edge source (global node id b*NN+src)
__device__ float g_sp [(long)BB * NN * NN];  // spilled score rows (128MB, streaming)

// ---------------------------------------------------------------------------
// Prep: build WT[f][d] = {Wq[d][f], Wk[d-64][f], Wg[d-128][f]}; init deg=2
// (module self-loop + GCNConv internal self-loop). FF*MTOT == BB*NN == 32768.
// ---------------------------------------------------------------------------
__global__ void k_prep(const float* __restrict__ Wq, const float* __restrict__ Wk,
                       const float* __restrict__ Wg) {
    int idx = blockIdx.x * blockDim.x + threadIdx.x;   // 0..32767
    int f = idx >> 8;
    int d = idx & 255;
    float v;
    if (d < 64)       v = Wq[d * FF + f];
    else if (d < 128) v = Wk[(d - 64) * FF + f];
    else              v = Wg[(d - 128) * FF + f];
    g_WT[f * MTOT + d] = v;
    g_deg[idx] = 2.0f;
}

// zero the CSR fill cursors
__global__ void k_zero() {
    g_cur[blockIdx.x * 256 + threadIdx.x] = 0;
}

// ---------------------------------------------------------------------------
// GEMM body: C[d][n] = sum_f WT[f][d] * x[b][f][n] for one 64x64 (m,n) tile.
// m0<64: q (+bq); m0 in [64,128): kkT transposed (+bk); m0>=128: h (no bias).
// Whole K=128 operand pair loaded once via cp.async, then one uninterrupted
// FFMA2 mainloop. Shared by k_qkh (q/k tiles) and k_fused h-blocks.
// ---------------------------------------------------------------------------
__device__ __forceinline__ void qkh_body(float* sq, const float* __restrict__ x,
                                         const float* __restrict__ bq,
                                         const float* __restrict__ bk,
                                         int m0, int n0, int b, int tid) {
    float* As = sq;               // [128][64]  32KB  (k-major, m inner)
    float* Bs = sq + FF * 64;     // [128][64]  32KB
    const int tx = tid & 15;    // n quad
    const int ty = tid >> 4;    // m quad

    const unsigned int As_s = (unsigned int)__cvta_generic_to_shared(As);
    const unsigned int Bs_s = (unsigned int)__cvta_generic_to_shared(Bs);
    for (int u = tid; u < FF * 16; u += 256) {
        int k = u >> 4, g = u & 15;
        unsigned int soff = (unsigned)(k * 64 + g * 4) * 4;
        cp16(As_s + soff, &g_WT[k * MTOT + m0 + g * 4]);
        cp16(Bs_s + soff, &x[((long)(b * FF + k)) * NN + n0 + g * 4]);
    }
    asm volatile("cp.async.commit_group;" ::: "memory");

    u64 acc2[4][2];             // [m][n-pair], each holds cols (0,1)/(2,3)
    #pragma unroll
    for (int i = 0; i < 4; i++) { acc2[i][0] = 0ull; acc2[i][1] = 0ull; }

    asm volatile("cp.async.wait_group 0;" ::: "memory");
    __syncthreads();

    #pragma unroll 8
    for (int k = 0; k < FF; k++) {
        float4 a  = *(const float4*)&As[k * 64 + ty * 4];
        ulonglong2 bb = *(const ulonglong2*)&Bs[k * 64 + tx * 4];  // one LDS.128
        u64 b0 = bb.x, b1 = bb.y;
        float av[4] = {a.x, a.y, a.z, a.w};
        #pragma unroll
        for (int i = 0; i < 4; i++) {
            u64 aa = pk2(av[i], av[i]);
            fma2(acc2[i][0], aa, b0);
            fma2(acc2[i][1], aa, b1);
        }
    }

    float acc[4][4];
    #pragma unroll
    for (int i = 0; i < 4; i++) {
        upk2(acc2[i][0], acc[i][0], acc[i][1]);
        upk2(acc2[i][1], acc[i][2], acc[i][3]);
    }

    const int d0 = m0 + ty * 4;   // combined dim base (multiple of 4)
    float4 bias = make_float4(0.f, 0.f, 0.f, 0.f);
    if (m0 == 0)       bias = *(const float4*)&bq[d0];
    else if (m0 == 64) bias = *(const float4*)&bk[d0 - 64];

    if (m0 == 64) {
        // k part: store transposed rows [d][n], float4 along n
        float bb4[4] = {bias.x, bias.y, bias.z, bias.w};
        #pragma unroll
        for (int i = 0; i < 4; i++) {
            int dd = d0 - 64 + i;
            float4 v = make_float4(acc[i][0] + bb4[i], acc[i][1] + bb4[i],
                                   acc[i][2] + bb4[i], acc[i][3] + bb4[i]);
            *(float4*)&g_kkT[((long)(b * DG + dd)) * NN + n0 + tx * 4] = v;
        }
    } else {
        #pragma unroll
        for (int jj = 0; jj < 4; jj++) {
            int n = n0 + tx * 4 + jj;
            float4 v = make_float4(acc[0][jj] + bias.x, acc[1][jj] + bias.y,
                                   acc[2][jj] + bias.z, acc[3][jj] + bias.w);
            long nodeBase = (long)(b * NN + n);
            if (m0 == 0) *(float4*)&g_q [nodeBase * DG + d0]         = v;
            else         *(float4*)&g_h [nodeBase * FF + (d0 - 128)] = v;
        }
    }
}

// q/k tiles only (m0 in {0, 64}); the h tiles ride inside k_fused.
__global__ void __launch_bounds__(256, 3) k_qkh(const float* __restrict__ x,
                                                const float* __restrict__ bq,
                                                const float* __restrict__ bk) {
    extern __shared__ __align__(16) float sdyn[];
    qkh_body(sdyn, x, bq, bk, blockIdx.x * 64, blockIdx.y * 64, blockIdx.z,
             threadIdx.x);
}

// ---------------------------------------------------------------------------
// Top-15 selection. Per-lane candidates seeded from an inline-maintained
// top-2; 15 warp-argmax extractions with (value desc, index asc) order
// matching jax.lax.top_k. When a lane must yield its 3rd+ value it rescans
// its own 32 scores from the global spill row (rare: E ~0.44/row).
// ---------------------------------------------------------------------------
__device__ __forceinline__ void select15(float b1v, int b1i, float b2v, int b2i,
                                         const float* __restrict__ row_sp,
                                         int lane, int b, int r) {
    const float NEG = -CUDART_INF_F;
    const int BIGI = 1 << 30;
    float lv = CUDART_INF_F; int li = -1;    // lane's last extracted (exclusion bound)
    float cv = b1v; int ci = b1i;            // candidate
    float sv = b2v; int si = b2i;            // spare
    for (int it = 0; it < TK; it++) {
        float mv = cv; int mi = ci;
        #pragma unroll
        for (int off = 16; off; off >>= 1) {
            float ov = __shfl_xor_sync(0xffffffffu, mv, off);
            int   oi = __shfl_xor_sync(0xffffffffu, mi, off);
            if (ov > mv || (ov == mv && oi < mi)) { mv = ov; mi = oi; }
        }
        if (lane == 0) {
            g_topk[(b * NN + r) * TK + it] = mi;
            atomicAdd(&g_deg[b * NN + mi], 1.0f);   // integer-valued: exact
        }
        if (ci == mi) {                      // unique owner
            lv = mv; li = mi;
            cv = sv; ci = si; sv = NEG; si = BIGI;
        }
        bool need = (ci == BIGI);
        if (__any_sync(0xffffffffu, need)) {
            if (need) {
                cv = NEG; ci = BIGI;
                #pragma unroll
                for (int t8 = 0; t8 < 8; t8++) {
                    float4 vv = __ldg((const float4*)&row_sp[t8 * 128 + lane * 4]);
                    float va[4] = {vv.x, vv.y, vv.z, vv.w};
                    #pragma unroll
                    for (int j = 0; j < 4; j++) {
                        int col = t8 * 128 + lane * 4 + j;
                        float v = va[j];
                        bool after  = (v < lv) || (v == lv && col > li);
                        bool better = (v > cv) || (v == cv && col < ci);
                        if (after && better) { cv = v; ci = col; }
                    }
                }
            }
        }
    }
}

// ---------------------------------------------------------------------------
// Topk body — UNCHANGED datapath from R13/R14 (best measured: 221 us).
// 4 rows/warp + cp.async double-buffered k-tile prefetch. 1/sqrt(DG) scale
// omitted (top-k invariant). Diagonal masked to -inf.
// ---------------------------------------------------------------------------
__device__ __forceinline__ void topk_body(float* sdyn, int b, int r0,
                                          int tid) {
    float* qs  = sdyn;                    // [32][DG]  8KB
    float* ks0 = sdyn + 32 * DG;          // [DG][132] 33.8KB
    float* ks1 = ks0 + DG * 132;          // [DG][132] 33.8KB
    const int lane = tid & 31;
    const int w    = tid >> 5;
    const int rbase = r0 + 4 * w;

    for (int idx = tid; idx < 32 * DG; idx += 256)
        qs[idx] = g_q[(b * NN + r0 + (idx >> 6)) * DG + (idx & 63)];  // idx=row*64+d

    const unsigned int ks0_s = (unsigned int)__cvta_generic_to_shared(ks0);
    const unsigned int ks1_s = (unsigned int)__cvta_generic_to_shared(ks1);

    // prefetch tile 0 into ks0
    {
        for (int u = tid; u < DG * 32; u += 256) {
            int d = u >> 5, ms = u & 31;
            cp16(ks0_s + (unsigned)(d * 132 + ms * 4) * 4,
                 &g_kkT[((long)(b * DG + d)) * NN + ms * 4]);
        }
        asm volatile("cp.async.commit_group;" ::: "memory");
    }

    const float NEG = -CUDART_INF_F;
    const int BIGI = 1 << 30;
    float b1v[4], b2v[4]; int b1i[4], b2i[4];
    #pragma unroll
    for (int i = 0; i < 4; i++) { b1v[i] = NEG; b1i[i] = BIGI; b2v[i] = NEG; b2i[i] = BIGI; }

    const long spbase = ((long)(b * NN)) << 10;
    const float* qrow = &qs[4 * w * DG];

    #pragma unroll
    for (int t = 0; t < 8; t++) {
        const int m0 = t * 128;
        const float* kcur = (t & 1) ? ks1 : ks0;
        asm volatile("cp.async.wait_group 0;" ::: "memory");
        __syncthreads();                       // tile t resident block-wide
        if (t < 7) {                           // prefetch tile t+1 into other buf
            unsigned int dst_s = (t & 1) ? ks0_s : ks1_s;
            const int m1 = m0 + 128;
            for (int u = tid; u < DG * 32; u += 256) {
                int d = u >> 5, ms = u & 31;
                cp16(dst_s + (unsigned)(d * 132 + ms * 4) * 4,
                     &g_kkT[((long)(b * DG + d)) * NN + m1 + ms * 4]);
            }
            asm volatile("cp.async.commit_group;" ::: "memory");
        }

        u64 accA[4] = {0ull, 0ull, 0ull, 0ull};   // rows 0..3, cols (lane*4+0,+1)
        u64 accB[4] = {0ull, 0ull, 0ull, 0ull};   // rows 0..3, cols (lane*4+2,+3)

        #pragma unroll 4
        for (int d4 = 0; d4 < DG; d4 += 4) {
            float4 q0 = *(const float4*)&qrow[0 * DG + d4];   // broadcast LDS.128
            float4 q1 = *(const float4*)&qrow[1 * DG + d4];
            float4 q2 = *(const float4*)&qrow[2 * DG + d4];
            float4 q3 = *(const float4*)&qrow[3 * DG + d4];
            float qv0[4] = {q0.x, q0.y, q0.z, q0.w};
            float qv1[4] = {q1.x, q1.y, q1.z, q1.w};
            float qv2[4] = {q2.x, q2.y, q2.z, q2.w};
            float qv3[4] = {q3.x, q3.y, q3.z, q3.w};
            #pragma unroll
            for (int j = 0; j < 4; j++) {
                ulonglong2 kk = *(const ulonglong2*)&kcur[(d4 + j) * 132 + lane * 4];
                u64 kA = kk.x, kB = kk.y;                     // one LDS.128
                u64 qq0 = pk2(qv0[j], qv0[j]);
                u64 qq1 = pk2(qv1[j], qv1[j]);
                u64 qq2 = pk2(qv2[j], qv2[j]);
                u64 qq3 = pk2(qv3[j], qv3[j]);
                fma2(accA[0], qq0, kA);  fma2(accB[0], qq0, kB);
                fma2(accA[1], qq1, kA);  fma2(accB[1], qq1, kB);
                fma2(accA[2], qq2, kA);  fma2(accB[2], qq2, kB);
                fma2(accA[3], qq3, kA);  fma2(accB[3], qq3, kB);
            }
        }

        const int c0 = m0 + lane * 4;
        #pragma unroll
        for (int i = 0; i < 4; i++) {
            const int r = rbase + i;
            float v0, v1, v2, v3;
            upk2(accA[i], v0, v1); upk2(accB[i], v2, v3);
            if (c0 + 0 == r) v0 = NEG;
            if (c0 + 1 == r) v1 = NEG;
            if (c0 + 2 == r) v2 = NEG;
            if (c0 + 3 == r) v3 = NEG;
            // spill masked scores (streaming; read back only on rare rescans)
            *(float4*)&g_sp[spbase + (((long)r) << 10) + c0] =
                make_float4(v0, v1, v2, v3);
            // inline top-2 merge, ascending column order
            float va[4] = {v0, v1, v2, v3};
            #pragma unroll
            for (int j = 0; j < 4; j++) {
                float v = va[j]; int col = c0 + j;
                if (v > b1v[i])      { b2v[i] = b1v[i]; b2i[i] = b1i[i]; b1v[i] = v; b1i[i] = col; }
                else if (v > b2v[i]) { b2v[i] = v; b2i[i] = col; }
            }
        }
        __syncthreads();      // all warps done with kcur before it is refilled
    }

    #pragma unroll
    for (int i = 0; i < 4; i++) {
        const int r = rbase + i;
        select15(b1v[i], b1i[i], b2v[i], b2i[i],
                 &g_sp[spbase + (((long)r) << 10)], lane, b, r);
    }
}

// ---------------------------------------------------------------------------
// FUSED kernel: blocks 0..1023 = topk (dispatched first, seed all SMs);
// blocks 1024..2047 = h-GEMM tiles (m0 in {128,192}) which backfill the
// topk wave-quantization tail (1024 blocks / 444 concurrent = 3 waves, last
// only 31% full). No hazard: h-blocks write g_h; topk never reads g_h.
// ---------------------------------------------------------------------------
__global__ void __launch_bounds__(256, 3) k_fused(const float* __restrict__ x) {
    extern __shared__ __align__(16) float sdyn[];
    const int bid = blockIdx.x;
    if (bid < 1024) {
        topk_body(sdyn, bid >> 5, (bid & 31) * 32, threadIdx.x);
    } else {
        const int e = bid - 1024;            // 0..1023
        const int b   = e >> 5;              // batch
        const int rem = e & 31;
        const int m0  = 128 + (rem >> 4) * 64;   // {128, 192}
        const int n0  = (rem & 15) * 64;
        qkh_body(sdyn, x, nullptr, nullptr, m0, n0, b, threadIdx.x);
    }
}

// ---------------------------------------------------------------------------
// CSR offsets: per-batch exclusive scan of in-edge counts (deg-2); also dinv.
// One block per batch, 1024 threads (Hillis-Steele scan).
// ---------------------------------------------------------------------------
__global__ void __launch_bounds__(1024) k_offs() {
    __shared__ int s[1024];
    const int b = blockIdx.x, n = threadIdx.x, i = b * NN + n;
    float dg = g_deg[i];
    g_dinv[i] = rsqrtf(dg);
    int c = (int)dg - 2;
    s[n] = c;
    __syncthreads();
    for (int off = 1; off < 1024; off <<= 1) {
        int v = (n >= off) ? s[n - off] : 0;
        __syncthreads();
        s[n] += v;
        __syncthreads();
    }
    g_off[i] = b * NN * TK + s[n] - c;   // exclusive
}

// CSR fill: thread per edge, slot via int atomic cursor.
__global__ void k_fill() {
    int e = blockIdx.x * 256 + threadIdx.x;   // < NEDGE
    int bnsrc = e / TK;                       // b*NN + src
    int b = bnsrc >> 10;
    int tgt = g_topk[e];
    int bt = (b << 10) + tgt;
    int pos = atomicAdd(&g_cur[bt], 1);
    g_esrc[g_off[bt] + pos] = bnsrc;
}

// ---------------------------------------------------------------------------
// Gather: block per target node, 128 threads (one per feature). Coalesced
// 512B row reads of h[src], register accumulate, single store. No fp atomics.
// out_row = dinv[t] * ( sum_e h[src]*dinv[src] + 2*dinv[t]*h[t] )
// ---------------------------------------------------------------------------
__global__ void __launch_bounds__(128) k_gather() {
    const int t = blockIdx.x;        // global node id b*NN+n
    const int f = threadIdx.x;
    const float dt = g_dinv[t];
    const int cnt = (int)g_deg[t] - 2;
    const int off = g_off[t];
    float acc = 2.0f * dt * g_h[(long)t * FF + f];
    int j = 0;
    for (; j + 4 <= cnt; j += 4) {
        int s0 = g_esrc[off + j],     s1 = g_esrc[off + j + 1];
        int s2 = g_esrc[off + j + 2], s3 = g_esrc[off + j + 3];
        float e0 = g_dinv[s0], e1 = g_dinv[s1], e2 = g_dinv[s2], e3 = g_dinv[s3];
        float h0 = g_h[(long)s0 * FF + f], h1 = g_h[(long)s1 * FF + f];
        float h2 = g_h[(long)s2 * FF + f], h3 = g_h[(long)s3 * FF + f];
        acc += h0 * e0; acc += h1 * e1; acc += h2 * e2; acc += h3 * e3;
    }
    for (; j < cnt; j++) {
        int s = g_esrc[off + j];
        acc += g_h[(long)s * FF + f] * g_dinv[s];
    }
    g_acc[(long)t * FF + f] = acc * dt;
}

// out[b][f][n] = acc[b][n][f] + bg[f]   (tiled transpose)
__global__ void k_out(float* __restrict__ out, const float* __restrict__ bg) {
    __shared__ float tile[32][33];
    const int n0 = blockIdx.x * 32, f0 = blockIdx.y * 32, b = blockIdx.z;
    const int tx = threadIdx.x, ty = threadIdx.y;   // 32 x 8
    #pragma unroll
    for (int ii = 0; ii < 4; ii++) {
        int n = n0 + ty + ii * 8;
        tile[ty + ii * 8][tx] = g_acc[(long)(b * NN + n) * FF + f0 + tx];
    }
    __syncthreads();
    #pragma unroll
    for (int ii = 0; ii < 4; ii++) {
        int f = f0 + ty + ii * 8;
        out[(long)(b * FF + f) * NN + n0 + tx] = tile[tx][ty + ii * 8] + bg[f];
    }
}

// ---------------------------------------------------------------------------
extern "C" void kernel_launch(void* const* d_in, const int* in_sizes, int n_in,
                              void* d_out, int out_size) {
    const float* x  = (const float*)d_in[0];
    const float* Wq = (const float*)d_in[1];
    const float* bq = (const float*)d_in[2];
    const float* Wk = (const float*)d_in[3];
    const float* bk = (const float*)d_in[4];
    const float* Wg = (const float*)d_in[5];
    const float* bg = (const float*)d_in[6];
    float* out = (float*)d_out;

    const int TOPK_SMEM = (32 * DG + 2 * DG * 132) * 4;   // 75,776 B
    const int QKH_SMEM  = 2 * FF * 64 * 4;                // 65,536 B
    cudaFuncSetAttribute(k_fused, cudaFuncAttributeMaxDynamicSharedMemorySize,
                         TOPK_SMEM);
    cudaFuncSetAttribute(k_qkh, cudaFuncAttributeMaxDynamicSharedMemorySize,
                         QKH_SMEM);

    k_prep<<<(FF * MTOT) / 256, 256>>>(Wq, Wk, Wg);              // idx 0
    k_zero<<<(BB * NN) / 256, 256>>>();                          // idx 1
    k_qkh<<<dim3(2, NN / 64, BB), 256, QKH_SMEM>>>(x, bq, bk);   // idx 2 (q,k tiles)
    k_fused<<<2048, 256, TOPK_SMEM>>>(x);                        // idx 3 (ncu capture)
    k_offs<<<BB, 1024>>>();                                      // idx 4
    k_fill<<<NEDGE / 256, 256>>>();                              // idx 5
    k_gather<<<BB * NN, 128>>>();                                // idx 6
    k_out<<<dim3(NN / 32, FF / 32, BB), dim3(32, 8)>>>(out, bg); // idx 7
}